// round 13
// baseline (speedup 1.0000x reference)
#include <cuda_runtime.h>
#include <cuda_bf16.h>
#include <cstdint>

#define NTHR 256
#define TOKB 128
#define EXPN 64
#define CDIM 2048
#define BT   16384
#define BDIM 4
#define TOPK 6
#define NKS  128
#define CH   4
#define KSTEP_U32 1024
#define CHUNK_U32 (CH*KSTEP_U32)
#define LSTR 66
#define TAU  5.5e-3f
#define SMEM_BYTES (4*CHUNK_U32*4 + TOKB*LSTR*4)   // 65536 + 33792

// fix kernel dynamic smem layout (floats)
#define FWS_OFF  0                    // 64*129 = 8256 floats
#define FXS_OFF  8256                 // 32*132 = 4224
#define FLG_OFF  12480                // 256 (lgq / lg / red alias)
#define FTK_OFF  12736                // 32 ints
#define FIX_SMEM ((12736 + 32) * 4)   // 51072 B

__device__ float g_sums[BDIM * EXPN];
__device__ float g_cnts[BDIM * EXPN];
__device__ int   g_candcnt, g_fullcnt;
__device__ int   g_ctok[BT];
__device__ int   g_cid[BT * 8];
__device__ float g_cprob[BT * 8];
__device__ int   g_ffull[BT];
__device__ uint32_t wsg[NKS * KSTEP_U32];   // 512 KB packed 2-plane bf16 W fragments

static __device__ __forceinline__ void cp16(void* smem_ptr, const void* gptr) {
    unsigned saddr = (unsigned)__cvta_generic_to_shared(smem_ptr);
    asm volatile("cp.async.cg.shared.global [%0], [%1], 16;\n" :: "r"(saddr), "l"(gptr));
}
#define CP_COMMIT() asm volatile("cp.async.commit_group;\n" ::: "memory")

static __device__ __forceinline__ void mma16816(float* c, const uint32_t* a,
                                                uint32_t b0, uint32_t b1) {
    asm volatile("mma.sync.aligned.m16n8k16.row.col.f32.bf16.bf16.f32 "
        "{%0,%1,%2,%3}, {%4,%5,%6,%7}, {%8,%9}, {%0,%1,%2,%3};"
        : "+f"(c[0]), "+f"(c[1]), "+f"(c[2]), "+f"(c[3])
        : "r"(a[0]), "r"(a[1]), "r"(a[2]), "r"(a[3]), "r"(b0), "r"(b1));
}

// exact 2-way bf16 split of a float pair (prep only)
static __device__ __forceinline__ void split2(float f0, float f1,
                                              uint32_t& o0, uint32_t& o1) {
    __nv_bfloat162 b = __floats2bfloat162_rn(f0, f1);
    uint32_t u = *(uint32_t*)&b;
    o0 = u;
    float g0 = __int_as_float(u << 16);
    float g1 = __int_as_float(u & 0xffff0000u);
    __nv_bfloat162 c = __floats2bfloat162_rn(f0 - g0, f1 - g1);
    o1 = *(uint32_t*)&c;
}

static __device__ __forceinline__ uint32_t cvt2(float f0, float f1) {
    __nv_bfloat162 b = __floats2bfloat162_rn(f0, f1);
    return *(uint32_t*)&b;
}

// ---------------- W prep: 2-plane split, packed in B-fragment lane order ----------------
__global__ void prep_kernel(const float* __restrict__ w) {
    int id = blockIdx.x * 256 + threadIdx.x;
    if (id < BDIM * EXPN) { g_sums[id] = 0.f; g_cnts[id] = 0.f; }
    if (id == 0) { g_candcnt = 0; g_fullcnt = 0; }
    int s = id >> 8;
    int j = (id >> 5) & 7;
    int l = id & 31;
    int n  = 8 * j + (l >> 2);
    int k0 = s * 16 + (l & 3) * 2;
    const float* wr = w + (size_t)n * CDIM + k0;
    float2 flo = *(const float2*)wr;
    float2 fhi = *(const float2*)(wr + 8);
    uint32_t A, B, C, D;
    split2(flo.x, flo.y, A, B);
    split2(fhi.x, fhi.y, C, D);
    uint32_t base = (uint32_t)(((s * 4 + (j >> 1)) * 2 + (j & 1)) * 128 + l * 4);
    *(uint4*)&wsg[base] = make_uint4(A, C, B, D);   // (p0lo, p0hi, p1lo, p1hi)
}

// ---------------- main gate kernel: 2-term bf16 (x 1 plane, w 2 planes) ----------------
__global__ void __launch_bounds__(NTHR, 1)
gate_kernel(const float* __restrict__ x, float* __restrict__ out) {
    extern __shared__ char smem[];
    uint32_t* wbuf = (uint32_t*)smem;
    float* lsm = (float*)(smem + 4 * CHUNK_U32 * 4);
    __shared__ float s_sums[EXPN];
    __shared__ float s_cnt[EXPN];

    const int tid  = threadIdx.x;
    const int wid  = tid >> 5;
    const int lane = tid & 31;
    const int blk  = blockIdx.x;
    const int wg   = wid & 3;
    const int kh   = wid >> 2;

    if (tid < EXPN) { s_sums[tid] = 0.f; s_cnt[tid] = 0.f; }

    const int r  = lane >> 2;
    const int c0 = (lane & 3) * 2;
    const float* xr0 = x + ((size_t)blk * TOKB + wg * 32 + r) * CDIM + kh * 1024;
    const float* xr1 = xr0 + (size_t)16 * CDIM;

    float cacc[2][8][4];
#pragma unroll
    for (int m = 0; m < 2; m++)
#pragma unroll
        for (int j = 0; j < 8; j++)
#pragma unroll
            for (int q = 0; q < 4; q++) cacc[m][j][q] = 0.f;

    auto load2 = [&](int c) {
        int par = c & 1;
        const uint4* s0 = (const uint4*)(wsg + (size_t)c * CHUNK_U32);
        const uint4* s1 = (const uint4*)(wsg + (size_t)(16 + c) * CHUNK_U32);
        uint4* d0 = (uint4*)(wbuf + par * CHUNK_U32);
        uint4* d1 = (uint4*)(wbuf + (2 + par) * CHUNK_U32);
#pragma unroll
        for (int i = 0; i < 4; i++) cp16(d0 + tid + i * NTHR, s0 + tid + i * NTHR);
#pragma unroll
        for (int i = 0; i < 4; i++) cp16(d1 + tid + i * NTHR, s1 + tid + i * NTHR);
        CP_COMMIT();
    };

    load2(0);
    load2(1);

    for (int c = 0; c < 16; c++) {
        if (c + 1 < 16) asm volatile("cp.async.wait_group 1;\n" ::: "memory");
        else            asm volatile("cp.async.wait_group 0;\n" ::: "memory");
        __syncthreads();

        const uint32_t* wb = wbuf + (kh * 2 + (c & 1)) * CHUNK_U32;

#pragma unroll
        for (int kc = 0; kc < CH; kc++) {
            const int koff = (c * 4 + kc) * 16 + c0;
            uint32_t A[2][4];
#pragma unroll
            for (int m = 0; m < 2; m++) {
                const float* xp = (m == 0 ? xr0 : xr1) + koff;
                float2 l0 = *(const float2*)xp;
                float2 l1 = *(const float2*)(xp + 8 * CDIM);
                float2 h0 = *(const float2*)(xp + 8);
                float2 h1 = *(const float2*)(xp + 8 * CDIM + 8);
                A[m][0] = cvt2(l0.x, l0.y);
                A[m][1] = cvt2(l1.x, l1.y);
                A[m][2] = cvt2(h0.x, h0.y);
                A[m][3] = cvt2(h1.x, h1.y);
            }
            const uint4* wk = (const uint4*)(wb + kc * KSTEP_U32) + lane;
#pragma unroll
            for (int jp = 0; jp < 4; jp++) {
                uint4 G0 = wk[jp * 64];
                uint4 G1 = wk[jp * 64 + 32];
                float* e0 = cacc[0][2 * jp];
                float* o0 = cacc[0][2 * jp + 1];
                float* e1 = cacc[1][2 * jp];
                float* o1 = cacc[1][2 * jp + 1];
                // per-acc order: x0*w_plane0 then x0*w_plane1; reuse distance 4
                mma16816(e0, A[0], G0.x, G0.y);
                mma16816(o0, A[0], G1.x, G1.y);
                mma16816(e1, A[1], G0.x, G0.y);
                mma16816(o1, A[1], G1.x, G1.y);
                mma16816(e0, A[0], G0.z, G0.w);
                mma16816(o0, A[0], G1.z, G1.w);
                mma16816(e1, A[1], G0.z, G0.w);
                mma16816(o1, A[1], G1.z, G1.w);
            }
        }
        __syncthreads();
        if (c + 2 < 16) load2(c + 2);
    }

    // ---- combine k-halves ----
    if (kh == 0) {
#pragma unroll
        for (int m = 0; m < 2; m++)
#pragma unroll
            for (int j = 0; j < 8; j++) {
                int row = wg * 32 + m * 16 + r;
                int nb = 8 * j + c0;
                *(float2*)&lsm[row * LSTR + nb]       = make_float2(cacc[m][j][0], cacc[m][j][1]);
                *(float2*)&lsm[(row + 8) * LSTR + nb] = make_float2(cacc[m][j][2], cacc[m][j][3]);
            }
    }
    __syncthreads();
    if (kh == 1) {
#pragma unroll
        for (int m = 0; m < 2; m++)
#pragma unroll
            for (int j = 0; j < 8; j++) {
                int row = wg * 32 + m * 16 + r;
                int nb = 8 * j + c0;
                float2 a = *(float2*)&lsm[row * LSTR + nb];
                float2 b = *(float2*)&lsm[(row + 8) * LSTR + nb];
                *(float2*)&lsm[row * LSTR + nb]       = make_float2(a.x + cacc[m][j][0], a.y + cacc[m][j][1]);
                *(float2*)&lsm[(row + 8) * LSTR + nb] = make_float2(b.x + cacc[m][j][2], b.y + cacc[m][j][3]);
            }
    }
    __syncthreads();

    // ---- per-token epilogue: top-8 tracking + candidate/full flagging ----
    if (tid < TOKB) {
        float* row = lsm + tid * LSTR;

        float v0=-1e38f,v1=-1e38f,v2=-1e38f,v3=-1e38f,v4=-1e38f,v5=-1e38f,v6=-1e38f,v7=-1e38f;
        int   i0=0,i1=0,i2=0,i3=0,i4=0,i5=0,i6=0,i7=0;
        for (int e = 0; e < EXPN; e++) {
            float l = row[e];
            if (l > v7) {
                v7 = l; i7 = e;
                if (v7 > v6) { float t=v6; v6=v7; v7=t; int u=i6; i6=i7; i7=u;
                if (v6 > v5) { t=v5; v5=v6; v6=t; u=i5; i5=i6; i6=u;
                if (v5 > v4) { t=v4; v4=v5; v5=t; u=i4; i4=i5; i5=u;
                if (v4 > v3) { t=v3; v3=v4; v4=t; u=i3; i3=i4; i4=u;
                if (v3 > v2) { t=v2; v2=v3; v3=t; u=i2; i2=i3; i3=u;
                if (v2 > v1) { t=v1; v1=v2; v2=t; u=i1; i1=i2; i2=u;
                if (v1 > v0) { t=v0; v0=v1; v1=t; u=i0; i0=i1; i1=u; } } } } } } }
            }
        }

        float mg = v0 - v1;
        mg = fminf(mg, v1 - v2);
        mg = fminf(mg, v2 - v3);
        mg = fminf(mg, v3 - v4);
        mg = fminf(mg, v4 - v5);
        mg = fminf(mg, v5 - v6);
        const int tok = blk * TOKB + tid;

        float m = v0;
        float ssum = 0.f;
        for (int e = 0; e < EXPN; e++) {
            float p = expf(row[e] - m);
            ssum += p;
            row[e] = p;
        }
        float inv = 1.0f / ssum;

        if (mg < TAU) {
            if (v5 - v7 < TAU) {
                int slot = atomicAdd(&g_fullcnt, 1);
                g_ffull[slot] = tok;
            } else {
                int slot = atomicAdd(&g_candcnt, 1);
                g_ctok[slot] = tok;
                int b8 = slot * 8;
                g_cid[b8+0]=i0; g_cid[b8+1]=i1; g_cid[b8+2]=i2; g_cid[b8+3]=i3;
                g_cid[b8+4]=i4; g_cid[b8+5]=i5; g_cid[b8+6]=i6; g_cid[b8+7]=i7;
                g_cprob[b8+0]=row[i0]*inv; g_cprob[b8+1]=row[i1]*inv;
                g_cprob[b8+2]=row[i2]*inv; g_cprob[b8+3]=row[i3]*inv;
                g_cprob[b8+4]=row[i4]*inv; g_cprob[b8+5]=row[i5]*inv;
                g_cprob[b8+6]=row[i6]*inv; g_cprob[b8+7]=row[i7]*inv;
            }
        }

        const size_t g = (size_t)tok;
        float* out_idx = out;
        float* out_wgt = out + (size_t)BT * TOPK;

        out_idx[g * TOPK + 0] = (float)i0;
        out_idx[g * TOPK + 1] = (float)i1;
        out_idx[g * TOPK + 2] = (float)i2;
        out_idx[g * TOPK + 3] = (float)i3;
        out_idx[g * TOPK + 4] = (float)i4;
        out_idx[g * TOPK + 5] = (float)i5;

        out_wgt[g * TOPK + 0] = row[i0] * inv;
        out_wgt[g * TOPK + 1] = row[i1] * inv;
        out_wgt[g * TOPK + 2] = row[i2] * inv;
        out_wgt[g * TOPK + 3] = row[i3] * inv;
        out_wgt[g * TOPK + 4] = row[i4] * inv;
        out_wgt[g * TOPK + 5] = row[i5] * inv;

        for (int jj = 0; jj < EXPN; jj++) {
            int e = (tid + jj) & (EXPN - 1);
            atomicAdd(&s_sums[e], row[e] * inv);
        }
        atomicAdd(&s_cnt[i0], 1.0f);
        atomicAdd(&s_cnt[i1], 1.0f);
        atomicAdd(&s_cnt[i2], 1.0f);
        atomicAdd(&s_cnt[i3], 1.0f);
        atomicAdd(&s_cnt[i4], 1.0f);
        atomicAdd(&s_cnt[i5], 1.0f);
    }
    __syncthreads();

    if (tid < EXPN) {
        int b = blk >> 5;
        atomicAdd(&g_sums[b * EXPN + tid], s_sums[tid]);
        atomicAdd(&g_cnts[b * EXPN + tid], s_cnt[tid]);
    }
}

// ---------------- fix kernel: candidate re-sort + full recompute + aux ----------------
// exact logits replicate the validated R1 fp32 order: even/odd fmaf chains over ascending k.
__global__ void __launch_bounds__(256, 1)
fix_kernel(const float* __restrict__ x, const float* __restrict__ w,
           float* __restrict__ out) {
    extern __shared__ float sf[];
    float* ws  = sf + FWS_OFF;    // 64 x 129
    float* xs  = sf + FXS_OFF;    // 32 x 132
    float* lgq = sf + FLG_OFF;    // 256
    int*   tks = (int*)(sf + FTK_OFF);

    const int tid = threadIdx.x;
    float* out_idx = out;
    float* out_wgt = out + (size_t)BT * TOPK;

    // ---- Part A: 8-candidate exact re-sort (32 tokens per block-iteration) ----
    const int nc = g_candcnt;
    for (int base = blockIdx.x * 32; base < nc; base += gridDim.x * 32) {
        const int s = tid >> 3;   // token slot
        const int cc = tid & 7;   // candidate slot
        const int fi = base + s;
        const int fic = fi < nc ? fi : (nc - 1);
        const int eid = g_cid[fic * 8 + cc];

        __syncthreads();
        if (tid < 32) {
            int q = base + tid;
            tks[tid] = g_ctok[q < nc ? q : (nc - 1)];
        }
        __syncthreads();

        float accE = 0.f, accO = 0.f;
        for (int ch = 0; ch < 16; ch++) {
            __syncthreads();
            for (int i = tid; i < 64 * 32; i += 256) {
                int row = i >> 5, q = i & 31;
                float4 v = *(const float4*)(w + (size_t)row * CDIM + ch * 128 + q * 4);
                float* d = &ws[row * 129 + q * 4];
                d[0] = v.x; d[1] = v.y; d[2] = v.z; d[3] = v.w;
            }
            for (int i = tid; i < 32 * 32; i += 256) {
                int row = i >> 5, q = i & 31;
                float4 v = *(const float4*)(x + (size_t)tks[row] * CDIM + ch * 128 + q * 4);
                float* d = &xs[row * 132 + q * 4];
                d[0] = v.x; d[1] = v.y; d[2] = v.z; d[3] = v.w;
            }
            __syncthreads();
            const float* xr = &xs[s * 132];
            const float* wr = &ws[eid * 129];
#pragma unroll 8
            for (int kk = 0; kk < 128; kk += 2) {
                accE = fmaf(xr[kk],     wr[kk],     accE);
                accO = fmaf(xr[kk + 1], wr[kk + 1], accO);
            }
        }
        lgq[s * 8 + cc] = accE + accO;
        __syncthreads();

        if (tid < 32 && base + tid < nc) {
            const int fj = base + tid;
            const int tok = g_ctok[fj];
            float v[8]; int id8[8]; float p8[8];
#pragma unroll
            for (int j = 0; j < 8; j++) {
                v[j]   = lgq[tid * 8 + j];
                id8[j] = g_cid[fj * 8 + j];
                p8[j]  = g_cprob[fj * 8 + j];
            }
            // insertion sort desc by value, ties -> lower expert index first
#pragma unroll
            for (int i = 1; i < 8; i++) {
                float kv = v[i]; int ki = id8[i]; float kp = p8[i];
                int j = i - 1;
                while (j >= 0 && (v[j] < kv || (v[j] == kv && id8[j] > ki))) {
                    v[j+1] = v[j]; id8[j+1] = id8[j]; p8[j+1] = p8[j];
                    j--;
                }
                v[j+1] = kv; id8[j+1] = ki; p8[j+1] = kp;
            }
#pragma unroll
            for (int j = 0; j < TOPK; j++) {
                out_idx[(size_t)tok * TOPK + j] = (float)id8[j];
                out_wgt[(size_t)tok * TOPK + j] = p8[j];
            }
        }
    }
    __syncthreads();

    // ---- Part B: full 64-expert exact recompute (rare deep-ambiguity tokens) ----
    const int nfull = g_fullcnt;
    const int tg = tid >> 6;
    const int e  = tid & 63;
    float* lg = lgq;   // 4 x 64
    for (int base = blockIdx.x * 4; base < nfull; base += gridDim.x * 4) {
        const int fi  = base + tg;
        const int tok = g_ffull[fi < nfull ? fi : (nfull - 1)];

        float accE = 0.f, accO = 0.f;
        for (int ch = 0; ch < 16; ch++) {
            __syncthreads();
            for (int i = tid; i < 64 * 32; i += 256) {
                int row = i >> 5, q = i & 31;
                float4 v = *(const float4*)(w + (size_t)row * CDIM + ch * 128 + q * 4);
                float* d = &ws[row * 129 + q * 4];
                d[0] = v.x; d[1] = v.y; d[2] = v.z; d[3] = v.w;
            }
            __syncthreads();
            const float* xp = x + (size_t)tok * CDIM + ch * 128;
            const float* wr = &ws[e * 129];
#pragma unroll 8
            for (int kk = 0; kk < 128; kk += 2) {
                float2 xv = *(const float2*)(xp + kk);
                accE = fmaf(xv.x, wr[kk],     accE);
                accO = fmaf(xv.y, wr[kk + 1], accO);
            }
        }
        lg[tg * 64 + e] = accE + accO;
        __syncthreads();

        if (tid < 4 && base + tid < nfull) {
            const int t2 = g_ffull[base + tid];
            const float* row = lg + tid * 64;
            float v0=-1e38f,v1=-1e38f,v2=-1e38f,v3=-1e38f,v4=-1e38f,v5=-1e38f;
            int   i0=0,i1=0,i2=0,i3=0,i4=0,i5=0;
            for (int k = 0; k < EXPN; k++) {
                float l = row[k];
                if (l > v5) {
                    v5 = l; i5 = k;
                    if (v5 > v4) { float t=v4; v4=v5; v5=t; int u=i4; i4=i5; i5=u; }
                    if (v4 > v3) { float t=v3; v3=v4; v4=t; int u=i3; i3=i4; i4=u; }
                    if (v3 > v2) { float t=v2; v2=v3; v3=t; int u=i2; i2=i3; i3=u; }
                    if (v2 > v1) { float t=v1; v1=v2; v2=t; int u=i1; i1=i2; i2=u; }
                    if (v1 > v0) { float t=v0; v0=v1; v1=t; int u=i0; i0=i1; i1=u; }
                }
            }
            float m = v0;
            float ssum = 0.f;
            for (int k = 0; k < EXPN; k++) ssum += expf(row[k] - m);
            float inv = 1.0f / ssum;
            const size_t g = (size_t)t2;
            out_idx[g * TOPK + 0] = (float)i0;
            out_idx[g * TOPK + 1] = (float)i1;
            out_idx[g * TOPK + 2] = (float)i2;
            out_idx[g * TOPK + 3] = (float)i3;
            out_idx[g * TOPK + 4] = (float)i4;
            out_idx[g * TOPK + 5] = (float)i5;
            out_wgt[g * TOPK + 0] = expf(v0 - m) * inv;
            out_wgt[g * TOPK + 1] = expf(v1 - m) * inv;
            out_wgt[g * TOPK + 2] = expf(v2 - m) * inv;
            out_wgt[g * TOPK + 3] = expf(v3 - m) * inv;
            out_wgt[g * TOPK + 4] = expf(v4 - m) * inv;
            out_wgt[g * TOPK + 5] = expf(v5 - m) * inv;
        }
        __syncthreads();
    }

    // ---- Part C: aux loss (block 0) ----
    if (blockIdx.x == 0) {
        float* red = lgq;
        __syncthreads();
        red[tid] = g_cnts[tid] * g_sums[tid];
        __syncthreads();
#pragma unroll
        for (int s2 = 128; s2 > 0; s2 >>= 1) {
            if (tid < s2) red[tid] += red[tid + s2];
            __syncthreads();
        }
        if (tid == 0) {
            const float scale = (float)(0.001 * 64.0 / ((double)4 * 4096.0 * 6.0 * 4096.0));
            out[(size_t)BT * 12] = red[0] * scale;
        }
    }
}

extern "C" void kernel_launch(void* const* d_in, const int* in_sizes, int n_in,
                              void* d_out, int out_size) {
    const float* x = (const float*)d_in[0];
    const float* w = (const float*)d_in[1];
    float* out = (float*)d_out;

    cudaFuncSetAttribute(gate_kernel, cudaFuncAttributeMaxDynamicSharedMemorySize, SMEM_BYTES);
    cudaFuncSetAttribute(fix_kernel, cudaFuncAttributeMaxDynamicSharedMemorySize, FIX_SMEM);

    prep_kernel<<<128, 256>>>(w);
    gate_kernel<<<BT / TOKB, NTHR, SMEM_BYTES>>>(x, out);
    fix_kernel<<<128, 256, FIX_SMEM>>>(x, w, out);
}